// round 1
// baseline (speedup 1.0000x reference)
#include <cuda_runtime.h>
#include <math.h>

// Problem constants (fixed by setup_inputs)
#define NROWS 4096
#define DIM   512
#define BHALF 2048        // N/2
#define INV_TEMP 10.0f    // 1/0.1

#define BM 64
#define BN 64
#define BK 16
#define NCOLTILES (NROWS / BN)   // 64

// Scratch (device globals: allocation-free)
__device__ float g_f[NROWS * DIM];           // normalized features (8 MB)
__device__ float g_part[NCOLTILES * NROWS];  // per-(coltile,row) exp-sum partials (1 MB)
__device__ float g_pos[NROWS];               // sim[i, (i+B)%N]

// ---------------------------------------------------------------------------
// Kernel 1: L2-normalize each row. grid = NROWS blocks, 128 threads.
// ---------------------------------------------------------------------------
__global__ __launch_bounds__(128) void normalize_kernel(const float* __restrict__ in) {
    const int row = blockIdx.x;
    const int tid = threadIdx.x;          // 0..127, each handles one float4
    const float4* p = reinterpret_cast<const float4*>(in + (size_t)row * DIM);
    float4 v = p[tid];
    float ss = v.x * v.x + v.y * v.y + v.z * v.z + v.w * v.w;

    // warp reduce
    #pragma unroll
    for (int off = 16; off > 0; off >>= 1)
        ss += __shfl_down_sync(0xffffffffu, ss, off);

    __shared__ float sm[4];
    const int lane = tid & 31, wid = tid >> 5;
    if (lane == 0) sm[wid] = ss;
    __syncthreads();
    float total = sm[0] + sm[1] + sm[2] + sm[3];
    float nrm = sqrtf(total);
    float scale = 1.0f / fmaxf(nrm, 1e-12f);

    v.x *= scale; v.y *= scale; v.z *= scale; v.w *= scale;
    reinterpret_cast<float4*>(g_f + (size_t)row * DIM)[tid] = v;
}

// ---------------------------------------------------------------------------
// Kernel 2: fused sim-tile GEMM + exp-sum epilogue.
// grid = (NCOLTILES, NROWS/BM), 256 threads; thread (tx,ty) owns 4x4 sub-tile.
// ---------------------------------------------------------------------------
__global__ __launch_bounds__(256) void sim_exp_kernel() {
    __shared__ float As[BK][BM + 1];   // +1 pad: conflict-free transposed stores
    __shared__ float Bs[BK][BN + 1];

    const int bx = blockIdx.x;         // column tile
    const int by = blockIdx.y;         // row tile
    const int tid = threadIdx.x;
    const int tx = tid & 15;           // 0..15 -> columns
    const int ty = tid >> 4;           // 0..15 -> rows
    const int row0 = by * BM;
    const int col0 = bx * BN;

    float acc[4][4];
    #pragma unroll
    for (int i = 0; i < 4; i++)
        #pragma unroll
        for (int j = 0; j < 4; j++) acc[i][j] = 0.0f;

    const int lr = tid >> 2;           // 0..63: tile row handled by this thread's loads
    const int lq = tid & 3;            // 0..3 : which float4 chunk of the BK=16 slice

    for (int k0 = 0; k0 < DIM; k0 += BK) {
        // Stage A (rows) and B (cols) 64x16 slices, transposed into smem
        float4 va = *reinterpret_cast<const float4*>(
            &g_f[(size_t)(row0 + lr) * DIM + k0 + lq * 4]);
        As[lq * 4 + 0][lr] = va.x;
        As[lq * 4 + 1][lr] = va.y;
        As[lq * 4 + 2][lr] = va.z;
        As[lq * 4 + 3][lr] = va.w;
        float4 vb = *reinterpret_cast<const float4*>(
            &g_f[(size_t)(col0 + lr) * DIM + k0 + lq * 4]);
        Bs[lq * 4 + 0][lr] = vb.x;
        Bs[lq * 4 + 1][lr] = vb.y;
        Bs[lq * 4 + 2][lr] = vb.z;
        Bs[lq * 4 + 3][lr] = vb.w;
        __syncthreads();

        #pragma unroll
        for (int kk = 0; kk < BK; kk++) {
            float a[4], b[4];
            #pragma unroll
            for (int i = 0; i < 4; i++) a[i] = As[kk][ty * 4 + i];
            #pragma unroll
            for (int j = 0; j < 4; j++) b[j] = Bs[kk][tx * 4 + j];
            #pragma unroll
            for (int i = 0; i < 4; i++)
                #pragma unroll
                for (int j = 0; j < 4; j++)
                    acc[i][j] = fmaf(a[i], b[j], acc[i][j]);
        }
        __syncthreads();
    }

    // Epilogue: per-row exp-sum (diagonal excluded), capture positive.
    float esum[4];
    #pragma unroll
    for (int i = 0; i < 4; i++) esum[i] = 0.0f;

    #pragma unroll
    for (int i = 0; i < 4; i++) {
        const int gi = row0 + ty * 4 + i;
        const int posj = (gi + BHALF) & (NROWS - 1);
        #pragma unroll
        for (int j = 0; j < 4; j++) {
            const int gj = col0 + tx * 4 + j;
            const float s = acc[i][j];
            if (gj == posj) g_pos[gi] = s;        // unique writer per row
            if (gj != gi)  esum[i] += __expf(INV_TEMP * s);
        }
    }

    // Reduce esum across the 16 threads sharing ty (deterministic shuffle tree)
    #pragma unroll
    for (int i = 0; i < 4; i++) {
        #pragma unroll
        for (int off = 8; off > 0; off >>= 1)
            esum[i] += __shfl_down_sync(0xffffffffu, esum[i], off, 16);
    }
    if (tx == 0) {
        #pragma unroll
        for (int i = 0; i < 4; i++)
            g_part[(size_t)bx * NROWS + row0 + ty * 4 + i] = esum[i];
    }
}

// ---------------------------------------------------------------------------
// Kernel 3: finalize. 1 block, 256 threads: sum partials, loss, mean.
// ---------------------------------------------------------------------------
__global__ __launch_bounds__(256) void finalize_kernel(float* __restrict__ out) {
    const int tid = threadIdx.x;
    float local = 0.0f;
    for (int i = tid; i < NROWS; i += 256) {
        float s = 0.0f;
        #pragma unroll 8
        for (int c = 0; c < NCOLTILES; c++)
            s += g_part[(size_t)c * NROWS + i];
        local += logf(s) - INV_TEMP * g_pos[i];
    }
    // block reduce
    #pragma unroll
    for (int off = 16; off > 0; off >>= 1)
        local += __shfl_down_sync(0xffffffffu, local, off);
    __shared__ float sm[8];
    const int lane = tid & 31, wid = tid >> 5;
    if (lane == 0) sm[wid] = local;
    __syncthreads();
    if (tid == 0) {
        float t = 0.0f;
        #pragma unroll
        for (int w = 0; w < 8; w++) t += sm[w];
        out[0] = t / (float)NROWS;
    }
}

// ---------------------------------------------------------------------------
extern "C" void kernel_launch(void* const* d_in, const int* in_sizes, int n_in,
                              void* d_out, int out_size) {
    const float* features = (const float*)d_in[0];
    float* out = (float*)d_out;

    normalize_kernel<<<NROWS, 128>>>(features);
    dim3 grid(NCOLTILES, NROWS / BM);
    sim_exp_kernel<<<grid, 256>>>();
    finalize_kernel<<<1, 256>>>(out);
}

// round 3
// speedup vs baseline: 11.3978x; 11.3978x over previous
#include <cuda_runtime.h>
#include <cuda_bf16.h>
#include <stdint.h>
#include <math.h>

// ---------------- problem constants ----------------
#define NTOT  4096
#define DIM   512
#define BHALF 2048
#define INV_TEMP 10.0f

// ---------------- GEMM tiling ----------------
#define BM 128
#define BN 128
#define BKC 64            // K elements per pipeline chunk (128 bytes/row)
#define NKCH (DIM / BKC)  // 8
#define NCOLT (NTOT / 64) // 64 column-chunks (one per warp-column) for partials

// ---------------- device scratch (no allocs) ----------------
__device__ __nv_bfloat16 g_fb[NTOT * DIM];   // normalized features, bf16 (4 MB)
__device__ float g_part[NCOLT * NTOT];       // per-(colchunk,row) exp-sum partials
__device__ float g_pos[NTOT];                // sim[i, (i+B)%N]
__device__ float g_row[NTOT];                // per-row loss

// ---------------- helpers ----------------
static __device__ __forceinline__ uint32_t smem_u32(const void* p) {
    uint32_t a;
    asm("{ .reg .u64 t; cvta.to.shared.u64 t, %1; cvt.u32.u64 %0, t; }"
        : "=r"(a) : "l"(p));
    return a;
}

static __device__ __forceinline__ void ldm_x4(uint32_t r[4], uint32_t addr) {
    asm volatile("ldmatrix.sync.aligned.m8n8.x4.shared.b16 {%0,%1,%2,%3}, [%4];"
                 : "=r"(r[0]), "=r"(r[1]), "=r"(r[2]), "=r"(r[3]) : "r"(addr));
}

static __device__ __forceinline__ void mma16816(float c[4], const uint32_t a[4],
                                                uint32_t b0, uint32_t b1) {
    asm volatile(
        "mma.sync.aligned.m16n8k16.row.col.f32.bf16.bf16.f32 "
        "{%0,%1,%2,%3}, {%4,%5,%6,%7}, {%8,%9}, {%0,%1,%2,%3};"
        : "+f"(c[0]), "+f"(c[1]), "+f"(c[2]), "+f"(c[3])
        : "r"(a[0]), "r"(a[1]), "r"(a[2]), "r"(a[3]), "r"(b0), "r"(b1));
}

#define SWZ(off) ((off) ^ (((off) >> 3) & 0x70))

// ---------------------------------------------------------------------------
// Kernel 1: L2-normalize rows -> bf16. One warp per row. grid=512 x 256thr.
// ---------------------------------------------------------------------------
__global__ __launch_bounds__(256) void normalize_kernel(const float* __restrict__ in) {
    const int row = blockIdx.x * 8 + (threadIdx.x >> 5);
    const int lane = threadIdx.x & 31;
    const float4* p = reinterpret_cast<const float4*>(in + (size_t)row * DIM);

    float4 v[4];
    float ss = 0.f;
    #pragma unroll
    for (int i = 0; i < 4; ++i) {
        v[i] = p[lane + i * 32];
        ss += v[i].x * v[i].x + v[i].y * v[i].y + v[i].z * v[i].z + v[i].w * v[i].w;
    }
    #pragma unroll
    for (int off = 16; off > 0; off >>= 1)
        ss += __shfl_xor_sync(0xffffffffu, ss, off);

    const float scale = 1.0f / fmaxf(sqrtf(ss), 1e-12f);

    #pragma unroll
    for (int i = 0; i < 4; ++i) {
        __nv_bfloat162 p0 = __floats2bfloat162_rn(v[i].x * scale, v[i].y * scale);
        __nv_bfloat162 p1 = __floats2bfloat162_rn(v[i].z * scale, v[i].w * scale);
        uint2 o;
        o.x = *reinterpret_cast<uint32_t*>(&p0);
        o.y = *reinterpret_cast<uint32_t*>(&p1);
        *reinterpret_cast<uint2*>(g_fb + (size_t)row * DIM + (lane + i * 32) * 4) = o;
    }
}

// ---------------------------------------------------------------------------
// Kernel 2: bf16 HMMA GEMM tile 128x128 + fused exp-sum epilogue.
// 256 threads = 8 warps arranged 4(M) x 2(N); warp tile 32x64.
// ---------------------------------------------------------------------------
static __device__ __forceinline__ void load_chunk_async(uint32_t sbase, int b,
                                                        int tid, int row0, int col0,
                                                        int kc) {
    const __nv_bfloat16* F = g_fb;
    const uint32_t A = sbase + b * 32768;
    const uint32_t B = A + 16384;
    const int k0 = kc * BKC;

    #pragma unroll
    for (int it = 0; it < 4; ++it) {
        int u = tid + it * 256;
        int r = u >> 3, cg = u & 7;
        uint32_t so = SWZ((uint32_t)(r * 128 + cg * 16));
        const void* g = F + (size_t)(row0 + r) * DIM + k0 + cg * 8;
        asm volatile("cp.async.cg.shared.global [%0], [%1], 16;" :: "r"(A + so), "l"(g));
    }
    #pragma unroll
    for (int it = 0; it < 4; ++it) {
        int u = tid + it * 256;
        int r = u >> 3, cg = u & 7;
        uint32_t so = SWZ((uint32_t)(r * 128 + cg * 16));
        const void* g = F + (size_t)(col0 + r) * DIM + k0 + cg * 8;
        asm volatile("cp.async.cg.shared.global [%0], [%1], 16;" :: "r"(B + so), "l"(g));
    }
}

__global__ void __launch_bounds__(256, 2) sim_kernel() {
    extern __shared__ char sm_raw[];
    char* smem = (char*)(((uintptr_t)sm_raw + 1023) & ~(uintptr_t)1023);
    const uint32_t sbase = smem_u32(smem);

    const int tid = threadIdx.x;
    const int lane = tid & 31;
    const int wid = tid >> 5;
    const int wm = wid & 3;           // 0..3: 32-row slice
    const int wn = wid >> 2;          // 0..1: 64-col slice
    const int row0 = blockIdx.y * BM;
    const int col0 = blockIdx.x * BN;

    float acc[2][8][4];
    #pragma unroll
    for (int mi = 0; mi < 2; ++mi)
        #pragma unroll
        for (int ni = 0; ni < 8; ++ni)
            #pragma unroll
            for (int q = 0; q < 4; ++q) acc[mi][ni][q] = 0.f;

    // precompute per-lane ldmatrix base offsets (bytes, pre-swizzle)
    // A: 16x16 tiles; lanes 0-7 rows0-7/kseg0, 8-15 rows8-15/kseg0, 16-23 rows0-7/kseg1, 24-31 rows8-15/kseg1
    const int aRow = wm * 32 + ((lane >> 3) & 1) * 8 + (lane & 7);
    const uint32_t aKoff = (uint32_t)((lane >> 4) * 16);
    // B: lanes 0-7 n0-7/kseg0, 8-15 n0-7/kseg1, 16-23 n8-15/kseg0, 24-31 n8-15/kseg1
    const int bRow = wn * 64 + ((lane >> 4) & 1) * 8 + (lane & 7);
    const uint32_t bKoff = (uint32_t)(((lane >> 3) & 1) * 16);

    // ---- pipelined mainloop ----
    load_chunk_async(sbase, 0, tid, row0, col0, 0);
    asm volatile("cp.async.commit_group;" ::: "memory");

    #pragma unroll
    for (int c = 0; c < NKCH; ++c) {
        if (c < NKCH - 1) {
            load_chunk_async(sbase, (c + 1) & 1, tid, row0, col0, c + 1);
            asm volatile("cp.async.commit_group;" ::: "memory");
            asm volatile("cp.async.wait_group 1;" ::: "memory");
        } else {
            asm volatile("cp.async.wait_group 0;" ::: "memory");
        }
        __syncthreads();

        const uint32_t A = sbase + (c & 1) * 32768;
        const uint32_t B = A + 16384;

        #pragma unroll
        for (int kk = 0; kk < 4; ++kk) {
            uint32_t a[2][4];
            #pragma unroll
            for (int mi = 0; mi < 2; ++mi) {
                uint32_t off = (uint32_t)((aRow + mi * 16) * 128) + aKoff + kk * 32;
                ldm_x4(a[mi], A + SWZ(off));
            }
            uint32_t bb[4][4];
            #pragma unroll
            for (int nb = 0; nb < 4; ++nb) {
                uint32_t off = (uint32_t)((bRow + nb * 16) * 128) + bKoff + kk * 32;
                ldm_x4(bb[nb], B + SWZ(off));
            }
            #pragma unroll
            for (int mi = 0; mi < 2; ++mi)
                #pragma unroll
                for (int ni = 0; ni < 8; ++ni)
                    mma16816(acc[mi][ni], a[mi],
                             bb[ni >> 1][(ni & 1) * 2], bb[ni >> 1][(ni & 1) * 2 + 1]);
        }
        __syncthreads();
    }

    // ---- fused epilogue: exp-sum per row + positive capture ----
    #pragma unroll
    for (int mi = 0; mi < 2; ++mi) {
        #pragma unroll
        for (int half = 0; half < 2; ++half) {
            const int gi = row0 + wm * 32 + mi * 16 + half * 8 + (lane >> 2);
            const int posj = (gi + BHALF) & (NTOT - 1);
            float es = 0.f;
            #pragma unroll
            for (int ni = 0; ni < 8; ++ni) {
                #pragma unroll
                for (int q = 0; q < 2; ++q) {
                    float s = acc[mi][ni][half * 2 + q];
                    int gj = col0 + wn * 64 + ni * 8 + (lane & 3) * 2 + q;
                    if (gj == posj) g_pos[gi] = s;      // unique writer
                    es += (gj != gi) ? __expf(INV_TEMP * s) : 0.f;
                }
            }
            es += __shfl_xor_sync(0xffffffffu, es, 1);
            es += __shfl_xor_sync(0xffffffffu, es, 2);
            if ((lane & 3) == 0)
                g_part[(size_t)(blockIdx.x * 2 + wn) * NTOT + gi] = es;
        }
    }
}

// ---------------------------------------------------------------------------
// Kernel 3a: per-row loss. grid = 16 x 256 threads.
// ---------------------------------------------------------------------------
__global__ __launch_bounds__(256) void rowloss_kernel() {
    const int i = blockIdx.x * 256 + threadIdx.x;
    float s = 0.f;
    #pragma unroll 8
    for (int c = 0; c < NCOLT; ++c)
        s += g_part[(size_t)c * NTOT + i];
    g_row[i] = logf(s) - INV_TEMP * g_pos[i];
}

// ---------------------------------------------------------------------------
// Kernel 3b: final mean. 1 block, 256 threads.
// ---------------------------------------------------------------------------
__global__ __launch_bounds__(256) void reduce_kernel(float* __restrict__ out) {
    const int tid = threadIdx.x;
    float local = 0.f;
    for (int i = tid; i < NTOT; i += 256) local += g_row[i];
    #pragma unroll
    for (int off = 16; off > 0; off >>= 1)
        local += __shfl_xor_sync(0xffffffffu, local, off);
    __shared__ float sm[8];
    if ((tid & 31) == 0) sm[tid >> 5] = local;
    __syncthreads();
    if (tid == 0) {
        float t = 0.f;
        #pragma unroll
        for (int w = 0; w < 8; ++w) t += sm[w];
        out[0] = t / (float)NTOT;
    }
}

// ---------------------------------------------------------------------------
extern "C" void kernel_launch(void* const* d_in, const int* in_sizes, int n_in,
                              void* d_out, int out_size) {
    (void)in_sizes; (void)n_in; (void)out_size;
    const float* features = (const float*)d_in[0];
    float* out = (float*)d_out;

    const int dyn_smem = 64 * 1024 + 1024;
    static bool attr_set = false;
    if (!attr_set) {
        cudaFuncSetAttribute(sim_kernel, cudaFuncAttributeMaxDynamicSharedMemorySize,
                             dyn_smem);
        attr_set = true;
    }

    normalize_kernel<<<NTOT / 8, 256>>>(features);
    sim_kernel<<<dim3(NTOT / BN, NTOT / BM), 256, dyn_smem>>>();
    rowloss_kernel<<<16, 256>>>();
    reduce_kernel<<<1, 256>>>(out);
}

// round 4
// speedup vs baseline: 16.9949x; 1.4911x over previous
#include <cuda_runtime.h>
#include <cuda_bf16.h>
#include <stdint.h>
#include <math.h>

// ---------------- problem constants ----------------
#define NTOT  4096
#define DIM   512
#define BHALF 2048
#define INV_TEMP 10.0f

// ---------------- GEMM tiling ----------------
#define BM 128
#define BN 128
#define BKC 64            // K elements per pipeline chunk (128 bytes/row)
#define NKCH (DIM / BKC)  // 8
#define NCHUNK 32         // 128-wide column chunks for partials
#define NTILES 528        // 32*33/2 triangular tiles

// ---------------- device scratch (no allocs) ----------------
__device__ __nv_bfloat16 g_fb[NTOT * DIM];     // normalized features, bf16 (4 MB)
__device__ float g_part[NCHUNK * NTOT];        // per-(chunk,row) exp-sum partials
__device__ float g_pos[NTOT];                  // sim[i, (i+B)%N]
__device__ float g_blk[16];                    // finalize block partials
__device__ unsigned g_ctr = 0;                 // finalize completion counter

// ---------------- helpers ----------------
static __device__ __forceinline__ uint32_t smem_u32(const void* p) {
    uint32_t a;
    asm("{ .reg .u64 t; cvta.to.shared.u64 t, %1; cvt.u32.u64 %0, t; }"
        : "=r"(a) : "l"(p));
    return a;
}

static __device__ __forceinline__ void ldm_x4(uint32_t r[4], uint32_t addr) {
    asm volatile("ldmatrix.sync.aligned.m8n8.x4.shared.b16 {%0,%1,%2,%3}, [%4];"
                 : "=r"(r[0]), "=r"(r[1]), "=r"(r[2]), "=r"(r[3]) : "r"(addr));
}

static __device__ __forceinline__ void mma16816(float c[4], const uint32_t a[4],
                                                uint32_t b0, uint32_t b1) {
    asm volatile(
        "mma.sync.aligned.m16n8k16.row.col.f32.bf16.bf16.f32 "
        "{%0,%1,%2,%3}, {%4,%5,%6,%7}, {%8,%9}, {%0,%1,%2,%3};"
        : "+f"(c[0]), "+f"(c[1]), "+f"(c[2]), "+f"(c[3])
        : "r"(a[0]), "r"(a[1]), "r"(a[2]), "r"(a[3]), "r"(b0), "r"(b1));
}

#define SWZ(off) ((off) ^ (((off) >> 3) & 0x70))

// ---------------------------------------------------------------------------
// Kernel 1: L2-normalize rows -> bf16. One warp per row.
// ---------------------------------------------------------------------------
__global__ __launch_bounds__(256) void normalize_kernel(const float* __restrict__ in) {
    const int row = blockIdx.x * 8 + (threadIdx.x >> 5);
    const int lane = threadIdx.x & 31;
    const float4* p = reinterpret_cast<const float4*>(in + (size_t)row * DIM);

    float4 v[4];
    float ss = 0.f;
    #pragma unroll
    for (int i = 0; i < 4; ++i) {
        v[i] = p[lane + i * 32];
        ss += v[i].x * v[i].x + v[i].y * v[i].y + v[i].z * v[i].z + v[i].w * v[i].w;
    }
    #pragma unroll
    for (int off = 16; off > 0; off >>= 1)
        ss += __shfl_xor_sync(0xffffffffu, ss, off);

    const float scale = 1.0f / fmaxf(sqrtf(ss), 1e-12f);

    #pragma unroll
    for (int i = 0; i < 4; ++i) {
        __nv_bfloat162 p0 = __floats2bfloat162_rn(v[i].x * scale, v[i].y * scale);
        __nv_bfloat162 p1 = __floats2bfloat162_rn(v[i].z * scale, v[i].w * scale);
        uint2 o;
        o.x = *reinterpret_cast<uint32_t*>(&p0);
        o.y = *reinterpret_cast<uint32_t*>(&p1);
        *reinterpret_cast<uint2*>(g_fb + (size_t)row * DIM + (lane + i * 32) * 4) = o;
    }
}

// ---------------------------------------------------------------------------
// Kernel 2: triangular bf16 HMMA GEMM (128x128 tiles, bx >= by) + dual-direction
// exp-sum epilogue (row partials + transposed column partials).
// ---------------------------------------------------------------------------
static __device__ __forceinline__ void load_chunk_async(uint32_t sbase, int b,
                                                        int tid, int row0, int col0,
                                                        int kc) {
    const __nv_bfloat16* F = g_fb;
    const uint32_t A = sbase + b * 32768;
    const uint32_t B = A + 16384;
    const int k0 = kc * BKC;

    #pragma unroll
    for (int it = 0; it < 4; ++it) {
        int u = tid + it * 256;
        int r = u >> 3, cg = u & 7;
        uint32_t so = SWZ((uint32_t)(r * 128 + cg * 16));
        const void* g = F + (size_t)(row0 + r) * DIM + k0 + cg * 8;
        asm volatile("cp.async.cg.shared.global [%0], [%1], 16;" :: "r"(A + so), "l"(g));
    }
    #pragma unroll
    for (int it = 0; it < 4; ++it) {
        int u = tid + it * 256;
        int r = u >> 3, cg = u & 7;
        uint32_t so = SWZ((uint32_t)(r * 128 + cg * 16));
        const void* g = F + (size_t)(col0 + r) * DIM + k0 + cg * 8;
        asm volatile("cp.async.cg.shared.global [%0], [%1], 16;" :: "r"(B + so), "l"(g));
    }
}

__global__ void __launch_bounds__(256, 2) sim_kernel() {
    extern __shared__ char sm_raw[];
    char* smem = (char*)(((uintptr_t)sm_raw + 1023) & ~(uintptr_t)1023);
    const uint32_t sbase = smem_u32(smem);

    // triangular decode: t -> (bx, by) with bx >= by, t = bx*(bx+1)/2 + by
    const int t = blockIdx.x;
    int bx = (int)((sqrtf(8.0f * (float)t + 1.0f) - 1.0f) * 0.5f);
    while ((bx + 1) * (bx + 2) / 2 <= t) ++bx;
    while (bx * (bx + 1) / 2 > t) --bx;
    const int by = t - bx * (bx + 1) / 2;

    const int tid = threadIdx.x;
    const int lane = tid & 31;
    const int wid = tid >> 5;
    const int wm = wid & 3;           // 0..3: 32-row slice
    const int wn = wid >> 2;          // 0..1: 64-col slice
    const int row0 = by * BM;
    const int col0 = bx * BN;

    float acc[2][8][4];
    #pragma unroll
    for (int mi = 0; mi < 2; ++mi)
        #pragma unroll
        for (int ni = 0; ni < 8; ++ni)
            #pragma unroll
            for (int q = 0; q < 4; ++q) acc[mi][ni][q] = 0.f;

    const int aRow = wm * 32 + ((lane >> 3) & 1) * 8 + (lane & 7);
    const uint32_t aKoff = (uint32_t)((lane >> 4) * 16);
    const int bRow = wn * 64 + ((lane >> 4) & 1) * 8 + (lane & 7);
    const uint32_t bKoff = (uint32_t)(((lane >> 3) & 1) * 16);

    // ---- pipelined mainloop ----
    load_chunk_async(sbase, 0, tid, row0, col0, 0);
    asm volatile("cp.async.commit_group;" ::: "memory");

    #pragma unroll
    for (int c = 0; c < NKCH; ++c) {
        if (c < NKCH - 1) {
            load_chunk_async(sbase, (c + 1) & 1, tid, row0, col0, c + 1);
            asm volatile("cp.async.commit_group;" ::: "memory");
            asm volatile("cp.async.wait_group 1;" ::: "memory");
        } else {
            asm volatile("cp.async.wait_group 0;" ::: "memory");
        }
        __syncthreads();

        const uint32_t A = sbase + (c & 1) * 32768;
        const uint32_t B = A + 16384;

        #pragma unroll
        for (int kk = 0; kk < 4; ++kk) {
            uint32_t a[2][4];
            #pragma unroll
            for (int mi = 0; mi < 2; ++mi) {
                uint32_t off = (uint32_t)((aRow + mi * 16) * 128) + aKoff + kk * 32;
                ldm_x4(a[mi], A + SWZ(off));
            }
            uint32_t bb[4][4];
            #pragma unroll
            for (int nb = 0; nb < 4; ++nb) {
                uint32_t off = (uint32_t)((bRow + nb * 16) * 128) + bKoff + kk * 32;
                ldm_x4(bb[nb], B + SWZ(off));
            }
            #pragma unroll
            for (int mi = 0; mi < 2; ++mi)
                #pragma unroll
                for (int ni = 0; ni < 8; ++ni)
                    mma16816(acc[mi][ni], a[mi],
                             bb[ni >> 1][(ni & 1) * 2], bb[ni >> 1][(ni & 1) * 2 + 1]);
        }
        __syncthreads();
    }

    // ---- epilogue: row exp-sums + transposed column exp-sums ----
    float* smem_row = reinterpret_cast<float*>(smem);          // [128][2]
    float* smem_col = reinterpret_cast<float*>(smem + 1024);   // [128][4]

    const int rbase = row0 + wm * 32;
    const int cbase = col0 + wn * 64;
    const bool isPosTile = (bx - by == 16);
    float erow[4] = {0.f, 0.f, 0.f, 0.f};

    #pragma unroll
    for (int ni = 0; ni < 8; ++ni) {
        #pragma unroll
        for (int q = 0; q < 2; ++q) {
            const int gj = cbase + ni * 8 + (lane & 3) * 2 + q;
            float ecol = 0.f;
            #pragma unroll
            for (int rg = 0; rg < 4; ++rg) {
                const int mi = rg >> 1, half = rg & 1;
                const float s = acc[mi][ni][half * 2 + q];
                const int gi = rbase + mi * 16 + half * 8 + (lane >> 2);
                if (isPosTile && gj == gi + BHALF) {
                    g_pos[gi] = s;       // unique writer (pair computed once)
                    g_pos[gj] = s;
                }
                const float e = (gj != gi) ? __expf(INV_TEMP * s) : 0.f;
                erow[rg] += e;
                ecol += e;
            }
            // column sum across the 8 row-groups of lanes
            ecol += __shfl_xor_sync(0xffffffffu, ecol, 4);
            ecol += __shfl_xor_sync(0xffffffffu, ecol, 8);
            ecol += __shfl_xor_sync(0xffffffffu, ecol, 16);
            if ((lane >> 2) == 0)
                smem_col[(wn * 64 + ni * 8 + (lane & 3) * 2 + q) * 4 + wm] = ecol;
        }
    }

    #pragma unroll
    for (int rg = 0; rg < 4; ++rg) {
        float e = erow[rg];
        e += __shfl_xor_sync(0xffffffffu, e, 1);
        e += __shfl_xor_sync(0xffffffffu, e, 2);
        if ((lane & 3) == 0) {
            const int mi = rg >> 1, half = rg & 1;
            const int lr = wm * 32 + mi * 16 + half * 8 + (lane >> 2);
            smem_row[lr * 2 + wn] = e;
        }
    }
    __syncthreads();

    if (tid < 128) {
        const float pr = smem_row[tid * 2] + smem_row[tid * 2 + 1];
        g_part[(size_t)bx * NTOT + row0 + tid] = pr;
        if (bx != by) {
            const float pc = smem_col[tid * 4 + 0] + smem_col[tid * 4 + 1] +
                             smem_col[tid * 4 + 2] + smem_col[tid * 4 + 3];
            g_part[(size_t)by * NTOT + col0 + tid] = pc;
        }
    }
}

// ---------------------------------------------------------------------------
// Kernel 3: fused finalize. grid = 16 x 256. Last block does the final
// deterministic fixed-order sum; counter self-resets for graph replay.
// ---------------------------------------------------------------------------
__global__ __launch_bounds__(256) void finalize_kernel(float* __restrict__ out) {
    const int tid = threadIdx.x;
    const int row = blockIdx.x * 256 + tid;

    float s = 0.f;
    #pragma unroll 8
    for (int c = 0; c < NCHUNK; ++c)
        s += g_part[(size_t)c * NTOT + row];
    float local = logf(s) - INV_TEMP * g_pos[row];

    #pragma unroll
    for (int off = 16; off > 0; off >>= 1)
        local += __shfl_xor_sync(0xffffffffu, local, off);
    __shared__ float sm[8];
    if ((tid & 31) == 0) sm[tid >> 5] = local;
    __syncthreads();

    if (tid == 0) {
        float bsum = 0.f;
        #pragma unroll
        for (int w = 0; w < 8; ++w) bsum += sm[w];
        g_blk[blockIdx.x] = bsum;
        __threadfence();
        const unsigned old = atomicAdd(&g_ctr, 1u);
        if (old == 15u) {
            __threadfence();
            float tot = 0.f;
            #pragma unroll
            for (int b = 0; b < 16; ++b) tot += g_blk[b];   // fixed order: deterministic
            out[0] = tot / (float)NTOT;
            g_ctr = 0u;   // reset for next graph replay
        }
    }
}

// ---------------------------------------------------------------------------
extern "C" void kernel_launch(void* const* d_in, const int* in_sizes, int n_in,
                              void* d_out, int out_size) {
    (void)in_sizes; (void)n_in; (void)out_size;
    const float* features = (const float*)d_in[0];
    float* out = (float*)d_out;

    const int dyn_smem = 64 * 1024 + 1024;
    static bool attr_set = false;
    if (!attr_set) {
        cudaFuncSetAttribute(sim_kernel, cudaFuncAttributeMaxDynamicSharedMemorySize,
                             dyn_smem);
        attr_set = true;
    }

    normalize_kernel<<<NTOT / 8, 256>>>(features);
    sim_kernel<<<NTILES, 256, dyn_smem>>>();
    finalize_kernel<<<16, 256>>>(out);
}

// round 5
// speedup vs baseline: 17.8614x; 1.0510x over previous
#include <cuda_runtime.h>
#include <cuda_bf16.h>
#include <stdint.h>
#include <math.h>

// ---------------- problem constants ----------------
#define NTOT  4096
#define DIM   512
#define BHALF 2048
#define INV_TEMP 10.0f

// ---------------- GEMM tiling ----------------
#define BM 128
#define BN 128
#define BKC 64            // K elements per pipeline chunk (128 bytes/row)
#define NKCH (DIM / BKC)  // 8
#define NCHUNK 32         // 128-wide column chunks for partials
#define NTILES 528        // 32*33/2 triangular tiles
#define STAGE 32768       // bytes per pipeline stage (A 16KB + B 16KB)

// ---------------- device scratch (no allocs) ----------------
__device__ __nv_bfloat16 g_fb[NTOT * DIM];     // normalized features, bf16 (4 MB)
__device__ float g_part[NCHUNK * NTOT];        // per-(chunk,row) exp-sum partials
__device__ float g_pos[NTOT];                  // sim[i, (i+B)%N]
__device__ float g_blk[32];                    // finalize block partials
__device__ unsigned g_ctr = 0;                 // finalize completion counter

// ---------------- helpers ----------------
static __device__ __forceinline__ uint32_t smem_u32(const void* p) {
    uint32_t a;
    asm("{ .reg .u64 t; cvta.to.shared.u64 t, %1; cvt.u32.u64 %0, t; }"
        : "=r"(a) : "l"(p));
    return a;
}

static __device__ __forceinline__ void ldm_x4(uint32_t r[4], uint32_t addr) {
    asm volatile("ldmatrix.sync.aligned.m8n8.x4.shared.b16 {%0,%1,%2,%3}, [%4];"
                 : "=r"(r[0]), "=r"(r[1]), "=r"(r[2]), "=r"(r[3]) : "r"(addr));
}

static __device__ __forceinline__ void mma16816(float c[4], const uint32_t a[4],
                                                uint32_t b0, uint32_t b1) {
    asm volatile(
        "mma.sync.aligned.m16n8k16.row.col.f32.bf16.bf16.f32 "
        "{%0,%1,%2,%3}, {%4,%5,%6,%7}, {%8,%9}, {%0,%1,%2,%3};"
        : "+f"(c[0]), "+f"(c[1]), "+f"(c[2]), "+f"(c[3])
        : "r"(a[0]), "r"(a[1]), "r"(a[2]), "r"(a[3]), "r"(b0), "r"(b1));
}

#define SWZ(off) ((off) ^ (((off) >> 3) & 0x70))

// ---------------------------------------------------------------------------
// Kernel 1: L2-normalize rows -> bf16. 64 threads (2 warps) per row.
// grid = 1024 x 256 threads (4 rows per block).
// ---------------------------------------------------------------------------
__global__ __launch_bounds__(256) void normalize_kernel(const float* __restrict__ in) {
    const int tid = threadIdx.x;
    const int rloc = tid >> 6;              // 0..3: row within block
    const int g = tid & 63;                 // 0..63: lane within row-group
    const int row = blockIdx.x * 4 + rloc;
    const float4* p = reinterpret_cast<const float4*>(in + (size_t)row * DIM);

    float4 v0 = p[g];
    float4 v1 = p[g + 64];
    float ss = v0.x * v0.x + v0.y * v0.y + v0.z * v0.z + v0.w * v0.w +
               v1.x * v1.x + v1.y * v1.y + v1.z * v1.z + v1.w * v1.w;

    #pragma unroll
    for (int off = 16; off > 0; off >>= 1)
        ss += __shfl_xor_sync(0xffffffffu, ss, off);

    __shared__ float sm[8];
    if ((tid & 31) == 0) sm[tid >> 5] = ss;
    __syncthreads();
    const float total = sm[rloc * 2] + sm[rloc * 2 + 1];
    const float scale = 1.0f / fmaxf(sqrtf(total), 1e-12f);

    __nv_bfloat162 a0 = __floats2bfloat162_rn(v0.x * scale, v0.y * scale);
    __nv_bfloat162 a1 = __floats2bfloat162_rn(v0.z * scale, v0.w * scale);
    __nv_bfloat162 b0 = __floats2bfloat162_rn(v1.x * scale, v1.y * scale);
    __nv_bfloat162 b1 = __floats2bfloat162_rn(v1.z * scale, v1.w * scale);
    uint2 oa, ob;
    oa.x = *reinterpret_cast<uint32_t*>(&a0);
    oa.y = *reinterpret_cast<uint32_t*>(&a1);
    ob.x = *reinterpret_cast<uint32_t*>(&b0);
    ob.y = *reinterpret_cast<uint32_t*>(&b1);
    *reinterpret_cast<uint2*>(g_fb + (size_t)row * DIM + g * 4) = oa;
    *reinterpret_cast<uint2*>(g_fb + (size_t)row * DIM + (g + 64) * 4) = ob;
}

// ---------------------------------------------------------------------------
// Kernel 2: triangular bf16 HMMA GEMM (128x128 tiles, bx >= by) + dual-direction
// exp-sum epilogue. 3-stage cp.async pipeline, one sync per K-chunk.
// ---------------------------------------------------------------------------
static __device__ __forceinline__ void load_chunk_async(uint32_t sbase, int buf,
                                                        int tid, int row0, int col0,
                                                        int kc) {
    const __nv_bfloat16* F = g_fb;
    const uint32_t A = sbase + buf * STAGE;
    const uint32_t B = A + 16384;
    const int k0 = kc * BKC;

    #pragma unroll
    for (int it = 0; it < 4; ++it) {
        int u = tid + it * 256;
        int r = u >> 3, cg = u & 7;
        uint32_t so = SWZ((uint32_t)(r * 128 + cg * 16));
        const void* g = F + (size_t)(row0 + r) * DIM + k0 + cg * 8;
        asm volatile("cp.async.cg.shared.global [%0], [%1], 16;" :: "r"(A + so), "l"(g));
    }
    #pragma unroll
    for (int it = 0; it < 4; ++it) {
        int u = tid + it * 256;
        int r = u >> 3, cg = u & 7;
        uint32_t so = SWZ((uint32_t)(r * 128 + cg * 16));
        const void* g = F + (size_t)(col0 + r) * DIM + k0 + cg * 8;
        asm volatile("cp.async.cg.shared.global [%0], [%1], 16;" :: "r"(B + so), "l"(g));
    }
    asm volatile("cp.async.commit_group;" ::: "memory");
}

__global__ void __launch_bounds__(256, 2) sim_kernel() {
    extern __shared__ char sm_raw[];
    char* smem = (char*)(((uintptr_t)sm_raw + 1023) & ~(uintptr_t)1023);
    const uint32_t sbase = smem_u32(smem);

    // triangular decode: t -> (bx, by) with bx >= by, t = bx*(bx+1)/2 + by
    const int t = blockIdx.x;
    int bx = (int)((sqrtf(8.0f * (float)t + 1.0f) - 1.0f) * 0.5f);
    while ((bx + 1) * (bx + 2) / 2 <= t) ++bx;
    while (bx * (bx + 1) / 2 > t) --bx;
    const int by = t - bx * (bx + 1) / 2;

    const int tid = threadIdx.x;
    const int lane = tid & 31;
    const int wid = tid >> 5;
    const int wm = wid & 3;           // 0..3: 32-row slice
    const int wn = wid >> 2;          // 0..1: 64-col slice
    const int row0 = by * BM;
    const int col0 = bx * BN;

    float acc[2][8][4];
    #pragma unroll
    for (int mi = 0; mi < 2; ++mi)
        #pragma unroll
        for (int ni = 0; ni < 8; ++ni)
            #pragma unroll
            for (int q = 0; q < 4; ++q) acc[mi][ni][q] = 0.f;

    const int aRow = wm * 32 + ((lane >> 3) & 1) * 8 + (lane & 7);
    const uint32_t aKoff = (uint32_t)((lane >> 4) * 16);
    const int bRow = wn * 64 + ((lane >> 4) & 1) * 8 + (lane & 7);
    const uint32_t bKoff = (uint32_t)(((lane >> 3) & 1) * 16);

    // ---- 3-stage pipelined mainloop, one sync per chunk ----
    load_chunk_async(sbase, 0, tid, row0, col0, 0);
    load_chunk_async(sbase, 1, tid, row0, col0, 1);

    #pragma unroll
    for (int c = 0; c < NKCH; ++c) {
        if (c < NKCH - 1) {
            asm volatile("cp.async.wait_group 1;" ::: "memory");
        } else {
            asm volatile("cp.async.wait_group 0;" ::: "memory");
        }
        __syncthreads();
        if (c + 2 < NKCH)
            load_chunk_async(sbase, (c + 2) % 3, tid, row0, col0, c + 2);

        const uint32_t A = sbase + (c % 3) * STAGE;
        const uint32_t B = A + 16384;

        #pragma unroll
        for (int kk = 0; kk < 4; ++kk) {
            uint32_t a[2][4];
            #pragma unroll
            for (int mi = 0; mi < 2; ++mi) {
                uint32_t off = (uint32_t)((aRow + mi * 16) * 128) + aKoff + kk * 32;
                ldm_x4(a[mi], A + SWZ(off));
            }
            uint32_t bb[4][4];
            #pragma unroll
            for (int nb = 0; nb < 4; ++nb) {
                uint32_t off = (uint32_t)((bRow + nb * 16) * 128) + bKoff + kk * 32;
                ldm_x4(bb[nb], B + SWZ(off));
            }
            #pragma unroll
            for (int mi = 0; mi < 2; ++mi)
                #pragma unroll
                for (int ni = 0; ni < 8; ++ni)
                    mma16816(acc[mi][ni], a[mi],
                             bb[ni >> 1][(ni & 1) * 2], bb[ni >> 1][(ni & 1) * 2 + 1]);
        }
    }

    // ---- epilogue: row exp-sums + transposed column exp-sums ----
    // (smem reuse: stage 0 region holds chunk 5 data, no longer read; the last
    //  compute (c=7) reads stage 1 only, so writing here races with nothing.)
    float* smem_row = reinterpret_cast<float*>(smem);          // [128][2]
    float* smem_col = reinterpret_cast<float*>(smem + 1024);   // [128][4]

    const int rbase = row0 + wm * 32;
    const int cbase = col0 + wn * 64;
    const bool isPosTile = (bx - by == 16);
    float erow[4] = {0.f, 0.f, 0.f, 0.f};

    #pragma unroll
    for (int ni = 0; ni < 8; ++ni) {
        #pragma unroll
        for (int q = 0; q < 2; ++q) {
            const int gj = cbase + ni * 8 + (lane & 3) * 2 + q;
            float ecol = 0.f;
            #pragma unroll
            for (int rg = 0; rg < 4; ++rg) {
                const int mi = rg >> 1, half = rg & 1;
                const float s = acc[mi][ni][half * 2 + q];
                const int gi = rbase + mi * 16 + half * 8 + (lane >> 2);
                if (isPosTile && gj == gi + BHALF) {
                    g_pos[gi] = s;       // unique writer (pair computed once)
                    g_pos[gj] = s;
                }
                const float e = (gj != gi) ? __expf(INV_TEMP * s) : 0.f;
                erow[rg] += e;
                ecol += e;
            }
            ecol += __shfl_xor_sync(0xffffffffu, ecol, 4);
            ecol += __shfl_xor_sync(0xffffffffu, ecol, 8);
            ecol += __shfl_xor_sync(0xffffffffu, ecol, 16);
            if ((lane >> 2) == 0)
                smem_col[(wn * 64 + ni * 8 + (lane & 3) * 2 + q) * 4 + wm] = ecol;
        }
    }

    #pragma unroll
    for (int rg = 0; rg < 4; ++rg) {
        float e = erow[rg];
        e += __shfl_xor_sync(0xffffffffu, e, 1);
        e += __shfl_xor_sync(0xffffffffu, e, 2);
        if ((lane & 3) == 0) {
            const int mi = rg >> 1, half = rg & 1;
            const int lr = wm * 32 + mi * 16 + half * 8 + (lane >> 2);
            smem_row[lr * 2 + wn] = e;
        }
    }
    __syncthreads();

    if (tid < 128) {
        const float pr = smem_row[tid * 2] + smem_row[tid * 2 + 1];
        g_part[(size_t)bx * NTOT + row0 + tid] = pr;
        if (bx != by) {
            const float pc = smem_col[tid * 4 + 0] + smem_col[tid * 4 + 1] +
                             smem_col[tid * 4 + 2] + smem_col[tid * 4 + 3];
            g_part[(size_t)by * NTOT + col0 + tid] = pc;
        }
    }
}

// ---------------------------------------------------------------------------
// Kernel 3: fused finalize. grid = 32 x 128 (one row per thread). Last block
// does the deterministic fixed-order final sum; counter self-resets.
// ---------------------------------------------------------------------------
__global__ __launch_bounds__(128) void finalize_kernel(float* __restrict__ out) {
    const int tid = threadIdx.x;
    const int row = blockIdx.x * 128 + tid;

    float s = 0.f;
    #pragma unroll
    for (int c = 0; c < NCHUNK; ++c)
        s += g_part[(size_t)c * NTOT + row];
    float local = logf(s) - INV_TEMP * g_pos[row];

    #pragma unroll
    for (int off = 16; off > 0; off >>= 1)
        local += __shfl_xor_sync(0xffffffffu, local, off);
    __shared__ float sm[4];
    if ((tid & 31) == 0) sm[tid >> 5] = local;
    __syncthreads();

    if (tid == 0) {
        float bsum = sm[0] + sm[1] + sm[2] + sm[3];
        g_blk[blockIdx.x] = bsum;
        __threadfence();
        const unsigned old = atomicAdd(&g_ctr, 1u);
        if (old == 31u) {
            __threadfence();
            float tot = 0.f;
            #pragma unroll
            for (int b = 0; b < 32; ++b) tot += g_blk[b];   // fixed order: deterministic
            out[0] = tot / (float)NTOT;
            g_ctr = 0u;   // reset for next graph replay
        }
    }
}

// ---------------------------------------------------------------------------
extern "C" void kernel_launch(void* const* d_in, const int* in_sizes, int n_in,
                              void* d_out, int out_size) {
    (void)in_sizes; (void)n_in; (void)out_size;
    const float* features = (const float*)d_in[0];
    float* out = (float*)d_out;

    const int dyn_smem = 3 * STAGE + 1024;   // 97 KB: 3-stage pipeline
    static bool attr_set = false;
    if (!attr_set) {
        cudaFuncSetAttribute(sim_kernel, cudaFuncAttributeMaxDynamicSharedMemorySize,
                             dyn_smem);
        attr_set = true;
    }

    normalize_kernel<<<NTOT / 4, 256>>>(features);
    sim_kernel<<<NTILES, 256, dyn_smem>>>();
    finalize_kernel<<<32, 128>>>(out);
}